// round 7
// baseline (speedup 1.0000x reference)
#include <cuda_runtime.h>
#include <cstdint>

#define THREADS 256

// ---- problem constants ----
#define Cc    4
#define Tt    1000
#define FQn   1025
#define Dd    384
#define INF   128      // W*C
#define Mrows 8000     // B*T
#define KB    45

// ---- tiling ----
#define MT    256      // rows per CTA (8 warps x 32 rows)
#define DC    32       // D chunk
#define NCH   (Dd / DC)   // 12

// ---- smem layout (uint32 units), MMA fragment order, weights double-buffered ----
#define OFF_X   0
#define SZ_X    (16*16*128)     // 32768 : 16 m-tiles x 16 k-tiles
#define SZ_WP1  (16*2*128)      // 4096 per buffer
#define OFF_WP  (OFF_X + SZ_X)
#define SZ_WQ1  (4*8*128)       // 4096 per buffer
#define OFF_WQ  (OFF_WP + 2*SZ_WP1)
#define OFF_H   (OFF_WQ + 2*SZ_WQ1)
#define SZ_H    (16*4*128)      // 8192
#define SMEM_U32 (OFF_H + SZ_H) // 57344 u32 = 224 KB

// Band tables (disjoint frequency groups)
__constant__ int c_start[KB] = {
    0,4,9,15,22,30,39,49,60,72,85,99,114,130,147,165,184,204,225,247,
    270,294,319,345,372,400,429,459,490,522,554,586,618,650,682,714,
    746,778,810,842,874,906,938,970,1002};
__constant__ int c_width[KB] = {
    4,5,6,7,8,9,10,11,12,13,14,15,16,17,18,19,20,21,22,23,
    24,25,26,27,28,29,30,31,32,32,32,32,32,32,32,32,
    32,32,32,32,32,32,32,32,23};

__device__ __forceinline__ uint32_t f2tf(float f) {
    uint32_t r;
    asm("cvt.rna.tf32.f32 %0, %1;" : "=r"(r) : "f"(f));
    return r;
}

__device__ __forceinline__ void mma8(float* c, const uint4 a, uint32_t b0, uint32_t b1) {
    asm volatile(
        "mma.sync.aligned.m16n8k8.row.col.f32.tf32.tf32.f32 "
        "{%0,%1,%2,%3},{%4,%5,%6,%7},{%8,%9},{%0,%1,%2,%3};"
        : "+f"(c[0]), "+f"(c[1]), "+f"(c[2]), "+f"(c[3])
        : "r"(a.x), "r"(a.y), "r"(a.z), "r"(a.w), "r"(b0), "r"(b1));
}

__global__ __launch_bounds__(THREADS, 1)
void bandsplit_mma(const float* __restrict__ x,
                   const float* __restrict__ w_pre,
                   const float* __restrict__ b_pre,
                   const float* __restrict__ w_post,
                   const float* __restrict__ b_post,
                   float* __restrict__ out)
{
    extern __shared__ uint32_t sm[];
    __shared__ float bpre_sh[2][DC];
    __shared__ float bpost_sh[INF];

    const int k     = blockIdx.y;
    const int tile0 = blockIdx.x * MT;
    const int tid   = threadIdx.x;
    const int warp  = tid >> 5;
    const int lane  = tid & 31;
    const int fs    = c_start[k];
    const int fw    = c_width[k];

    // band-sparsity limits (uniform across CTA; skipped work is exactly zero)
    const int kt_lim = (fw + 1) >> 1;   // GEMM1 K-tiles with any valid kk
    const int np_lim = (fw + 3) >> 2;   // GEMM2 N-pairs with any valid output
    const int nt_lim = kt_lim;          // valid output o-tiles of 8

    for (int i = tid; i < INF; i += THREADS) bpost_sh[i] = b_post[k * INF + i];

    // ---- gather X into A-fragment layout (tf32) ----
    for (int task = warp; task < MT * Cc; task += 8) {
        const int m  = task >> 2;
        const int c  = task & 3;
        const int mg = tile0 + m;
        const int w  = lane;
        const int kt = w >> 1;
        if (kt < kt_lim) {                 // fully-dead tiles never read
            float v = 0.0f;
            if (mg < Mrows && w < fw) {
                const int b = mg / Tt;
                const int t = mg - b * Tt;
                v = x[((size_t)(b * Cc + c) * Tt + t) * FQn + fs + w];
            }
            const int gm     = m >> 4;
            const int lane_s = ((m & 7) << 2) | c;
            const int reg    = ((w & 1) << 1) | ((m >> 3) & 1);
            sm[OFF_X + (((gm * 16 + kt) * 32 + lane_s) << 2) + reg] = f2tf(v);
        }
    }

    // GEMM2 accumulators: 2 m-tiles x 16 n-tiles x 4 regs
    float yacc[2][16][4];
    #pragma unroll
    for (int mt = 0; mt < 2; ++mt)
        #pragma unroll
        for (int nt = 0; nt < 16; ++nt)
            #pragma unroll
            for (int e = 0; e < 4; ++e) yacc[mt][nt][e] = 0.0f;

    // ---- weight chunk staging (into buffer bsel) ----
    auto stage = [&](int ch, int bsel) {
        const int dbase = ch * DC;
        uint32_t* WP = sm + OFF_WP + bsel * SZ_WP1;
        uint32_t* WQ = sm + OFF_WQ + bsel * SZ_WQ1;
        // w_pre chunk: only rows kk < kt_lim*8
        const int nrows = kt_lim * 8;
        for (int i = tid; i < nrows * 32; i += THREADS) {
            const int kk = i >> 5;
            const int d  = i & 31;
            const float v = w_pre[((size_t)k * INF + kk) * Dd + dbase + d];
            const int kt = kk >> 3, kr = kk & 7, nt = d >> 3, nc = d & 7;
            const int np = nt >> 1, p = nt & 1;
            const int lane_s = (nc << 2) | (kr & 3);
            const int reg    = (p << 1) | (kr >> 2);
            WP[(((kt * 2 + np) * 32 + lane_s) << 2) + reg] = f2tf(v);
        }
        // w_post chunk: only cols o < np_lim*16
        const int olim = np_lim * 16;
        for (int i = tid; i < DC * INF; i += THREADS) {
            const int o = i & 127;
            if (o < olim) {
                const int d = i >> 7;
                const float v = w_post[((size_t)k * Dd + dbase + d) * INF + o];
                const int kt = d >> 3, kr = d & 7, nt = o >> 3, nc = o & 7;
                const int np = nt >> 1, p = nt & 1;
                const int lane_s = (nc << 2) | (kr & 3);
                const int reg    = (p << 1) | (kr >> 2);
                WQ[(((kt * 8 + np) * 32 + lane_s) << 2) + reg] = f2tf(v);
            }
        }
        if (tid < DC) bpre_sh[bsel][tid] = b_pre[k * Dd + dbase + tid];
    };

    stage(0, 0);
    __syncthreads();

    for (int ch = 0; ch < NCH; ++ch) {
        const int buf = ch & 1;
        // prefetch next chunk into the other buffer (overlaps with this chunk's MMAs)
        if (ch + 1 < NCH) stage(ch + 1, buf ^ 1);

        const uint32_t* WP = sm + OFF_WP + buf * SZ_WP1;
        const uint32_t* WQ = sm + OFF_WQ + buf * SZ_WQ1;

        // ---- GEMM1: H[32 x DC] per warp, K limited to valid tiles ----
        float h[2][4][4];
        #pragma unroll
        for (int mt = 0; mt < 2; ++mt)
            #pragma unroll
            for (int nt = 0; nt < 4; ++nt)
                #pragma unroll
                for (int e = 0; e < 4; ++e) h[mt][nt][e] = 0.0f;

        {
            const uint4* XF  = (const uint4*)(sm + OFF_X);
            const uint4* WpF = (const uint4*)WP;
            for (int kt = 0; kt < kt_lim; ++kt) {
                const uint4 a0 = XF[((warp * 2 + 0) * 16 + kt) * 32 + lane];
                const uint4 a1 = XF[((warp * 2 + 1) * 16 + kt) * 32 + lane];
                #pragma unroll
                for (int np = 0; np < 2; ++np) {
                    const uint4 b = WpF[(kt * 2 + np) * 32 + lane];
                    mma8(h[0][np * 2],     a0, b.x, b.y);
                    mma8(h[1][np * 2],     a1, b.x, b.y);
                    mma8(h[0][np * 2 + 1], a0, b.z, b.w);
                    mma8(h[1][np * 2 + 1], a1, b.z, b.w);
                }
            }
        }

        // ---- repack H (+b_pre, tf32) into GEMM2 A-fragment layout (warp-private) ----
        #pragma unroll
        for (int e = 0; e < 4; ++e) {
            const int lane2 = (lane & 0x1C) | ((lane & 1) << 1) | (e & 1);
            const int reg2  = (((lane >> 1) & 1) << 1) | (e >> 1);
            const int col   = ((lane & 3) << 1) | (e & 1);
            #pragma unroll
            for (int mt = 0; mt < 2; ++mt)
                #pragma unroll
                for (int nt = 0; nt < 4; ++nt) {   // k-tiles of GEMM2 (D dense)
                    const int d = nt * 8 + col;
                    const float v = h[mt][nt][e] + bpre_sh[buf][d];
                    sm[OFF_H + ((((warp * 2 + mt) * 4 + nt) * 32 + lane2) << 2) + reg2] = f2tf(v);
                }
        }
        __syncwarp();

        // ---- GEMM2: Y += H * Wpost (N limited to valid pairs) ----
        {
            const uint4* HF  = (const uint4*)(sm + OFF_H);
            const uint4* WqF = (const uint4*)WQ;
            #pragma unroll
            for (int kt = 0; kt < 4; ++kt) {
                const uint4 a0 = HF[((warp * 2 + 0) * 4 + kt) * 32 + lane];
                const uint4 a1 = HF[((warp * 2 + 1) * 4 + kt) * 32 + lane];
                for (int np = 0; np < np_lim; ++np) {
                    const uint4 b = WqF[(kt * 8 + np) * 32 + lane];
                    mma8(yacc[0][np * 2],     a0, b.x, b.y);
                    mma8(yacc[1][np * 2],     a1, b.x, b.y);
                    mma8(yacc[0][np * 2 + 1], a0, b.z, b.w);
                    mma8(yacc[1][np * 2 + 1], a1, b.z, b.w);
                }
            }
        }

        // one barrier per chunk: protects next buffer's staging completeness
        // and this buffer's reuse two chunks from now
        __syncthreads();
    }

    // ---- epilogue: stage Y in smem (reuse X/WP region), then coalesced scatter ----
    float* Ybuf = (float*)sm;   // [m][c][w] : m stride 132, c stride 33
    #pragma unroll
    for (int e = 0; e < 4; ++e) {
        const int r   = (lane >> 2) + ((e >> 1) << 3);
        const int col = ((lane & 3) << 1) | (e & 1);
        #pragma unroll
        for (int mt = 0; mt < 2; ++mt) {
            const int m = warp * 32 + mt * 16 + r;
            for (int nt = 0; nt < nt_lim; ++nt) {
                const int o = nt * 8 + col;
                Ybuf[m * 132 + (o & 3) * 33 + (o >> 2)] = yacc[mt][nt][e] + bpost_sh[o];
            }
        }
    }
    __syncthreads();

    for (int task = warp; task < MT * Cc; task += 8) {
        const int m  = task >> 2;
        const int c  = task & 3;
        const int mg = tile0 + m;
        const int w  = lane;
        if (mg < Mrows && w < fw) {
            const int b = mg / Tt;
            const int t = mg - b * Tt;
            out[((size_t)(b * Cc + c) * Tt + t) * FQn + fs + w] = Ybuf[m * 132 + c * 33 + w];
        }
    }
}

extern "C" void kernel_launch(void* const* d_in, const int* in_sizes, int n_in,
                              void* d_out, int out_size)
{
    (void)in_sizes; (void)n_in; (void)out_size;
    const float* x      = (const float*)d_in[0];
    const float* w_pre  = (const float*)d_in[1];
    const float* b_pre  = (const float*)d_in[2];
    const float* w_post = (const float*)d_in[3];
    const float* b_post = (const float*)d_in[4];
    float* out = (float*)d_out;

    const size_t smem_bytes = (size_t)SMEM_U32 * sizeof(uint32_t);  // 224 KB
    cudaFuncSetAttribute(bandsplit_mma,
                         cudaFuncAttributeMaxDynamicSharedMemorySize,
                         (int)smem_bytes);

    dim3 grid((Mrows + MT - 1) / MT, KB);   // (32, 45)
    bandsplit_mma<<<grid, THREADS, smem_bytes>>>(x, w_pre, b_pre, w_post, b_post, out);
}

// round 8
// speedup vs baseline: 1.2094x; 1.2094x over previous
#include <cuda_runtime.h>
#include <cstdint>

#define THREADS 128

// ---- problem constants ----
#define Cc    4
#define Tt    1000
#define FQn   1025
#define Dd    384
#define INF   128      // W*C
#define Mrows 8000     // B*T
#define KB    45

// ---- tiling ----
#define MT    128      // rows per CTA (4 warps x 32 rows)
#define DC    32       // D chunk
#define NCH   (Dd / DC)   // 12

// ---- smem layout (uint32 units), MMA fragment order ----
#define OFF_X   0
#define SZ_X    (8*16*128)      // 16384 : 8 m-tiles x 16 k-tiles
#define OFF_WP  (OFF_X + SZ_X)
#define SZ_WP   (16*2*128)      // 4096  : 16 k-tiles x 2 n-pairs
#define OFF_WQ  (OFF_WP + SZ_WP)
#define SZ_WQ   (4*8*128)       // 4096  : 4 k-tiles x 8 n-pairs
#define OFF_H   (OFF_WQ + SZ_WQ)
#define SZ_H    (8*4*128)       // 4096  : 8 m-tiles x 4 k-tiles
#define SMEM_U32 (OFF_H + SZ_H)      // 28672 u32 = 112 KB -> 2 CTAs/SM

// Band tables (disjoint frequency groups)
__constant__ int c_start[KB] = {
    0,4,9,15,22,30,39,49,60,72,85,99,114,130,147,165,184,204,225,247,
    270,294,319,345,372,400,429,459,490,522,554,586,618,650,682,714,
    746,778,810,842,874,906,938,970,1002};
__constant__ int c_width[KB] = {
    4,5,6,7,8,9,10,11,12,13,14,15,16,17,18,19,20,21,22,23,
    24,25,26,27,28,29,30,31,32,32,32,32,32,32,32,32,
    32,32,32,32,32,32,32,32,23};

__device__ __forceinline__ uint32_t f2tf(float f) {
    uint32_t r;
    asm("cvt.rna.tf32.f32 %0, %1;" : "=r"(r) : "f"(f));
    return r;
}

__device__ __forceinline__ void mma8(float* c, const uint4 a, uint32_t b0, uint32_t b1) {
    asm volatile(
        "mma.sync.aligned.m16n8k8.row.col.f32.tf32.tf32.f32 "
        "{%0,%1,%2,%3},{%4,%5,%6,%7},{%8,%9},{%0,%1,%2,%3};"
        : "+f"(c[0]), "+f"(c[1]), "+f"(c[2]), "+f"(c[3])
        : "r"(a.x), "r"(a.y), "r"(a.z), "r"(a.w), "r"(b0), "r"(b1));
}

__global__ __launch_bounds__(THREADS, 2)
void bandsplit_mma(const float* __restrict__ x,
                   const float* __restrict__ w_pre,
                   const float* __restrict__ b_pre,
                   const float* __restrict__ w_post,
                   const float* __restrict__ b_post,
                   float* __restrict__ out)
{
    extern __shared__ uint32_t sm[];
    __shared__ float bpre_sh[DC];
    __shared__ float bpost_sh[INF];

    const int k     = blockIdx.y;
    const int tile0 = blockIdx.x * MT;
    const int tid   = threadIdx.x;
    const int warp  = tid >> 5;      // 0..3
    const int lane  = tid & 31;
    const int fs    = c_start[k];
    const int fw    = c_width[k];    // uniform per CTA

    for (int i = tid; i < INF; i += THREADS) bpost_sh[i] = b_post[k * INF + i];

    // ---- gather X into A-fragment layout (tf32) ----
    // one warp per (m, channel): lanes read consecutive freqs (coalesced)
    for (int task = warp; task < MT * Cc; task += 4) {
        const int m  = task >> 2;
        const int c  = task & 3;
        const int mg = tile0 + m;
        const int w  = lane;
        const int kt = w >> 1;
        if (2 * kt < fw) {               // fully-dead k-tiles never touched
            float v = 0.0f;
            if (mg < Mrows && w < fw) {
                const int b = mg / Tt;
                const int t = mg - b * Tt;
                v = x[((size_t)(b * Cc + c) * Tt + t) * FQn + fs + w];
            }
            const int gm     = m >> 4;   // 0..7
            const int lane_s = ((m & 7) << 2) | c;
            const int reg    = ((w & 1) << 1) | ((m >> 3) & 1);
            sm[OFF_X + (((gm * 16 + kt) * 32 + lane_s) << 2) + reg] = f2tf(v);
        }
    }

    // GEMM2 accumulators: 2 m-tiles x 16 n-tiles x 4 regs (all static indexing)
    float yacc[2][16][4];
    #pragma unroll
    for (int mt = 0; mt < 2; ++mt)
        #pragma unroll
        for (int nt = 0; nt < 16; ++nt)
            #pragma unroll
            for (int e = 0; e < 4; ++e) yacc[mt][nt][e] = 0.0f;

    for (int ch = 0; ch < NCH; ++ch) {
        const int dbase = ch * DC;
        __syncthreads();   // previous chunk's MMA reads of WP/WQ/H complete

        // ---- stage w_pre chunk [128 x DC] as B-fragments (dense, coalesced) ----
        for (int i = tid; i < 128 * DC; i += THREADS) {
            const int kk = i >> 5;
            const int d  = i & 31;
            const float v = w_pre[((size_t)k * INF + kk) * Dd + dbase + d];
            const int kt = kk >> 3, kr = kk & 7, nt = d >> 3, nc = d & 7;
            const int np = nt >> 1, p = nt & 1;
            const int lane_s = (nc << 2) | (kr & 3);
            const int reg    = (p << 1) | (kr >> 2);
            sm[OFF_WP + (((kt * 2 + np) * 32 + lane_s) << 2) + reg] = f2tf(v);
        }
        // ---- stage w_post chunk [DC x 128] as B-fragments ----
        for (int i = tid; i < DC * INF; i += THREADS) {
            const int d = i >> 7;
            const int o = i & 127;
            const float v = w_post[((size_t)k * Dd + dbase + d) * INF + o];
            const int kt = d >> 3, kr = d & 7, nt = o >> 3, nc = o & 7;
            const int np = nt >> 1, p = nt & 1;
            const int lane_s = (nc << 2) | (kr & 3);
            const int reg    = (p << 1) | (kr >> 2);
            sm[OFF_WQ + (((kt * 8 + np) * 32 + lane_s) << 2) + reg] = f2tf(v);
        }
        if (tid < DC) bpre_sh[tid] = b_pre[k * Dd + dbase + tid];
        __syncthreads();

        // ---- GEMM1: H[32 x DC] per warp; unrolled, uniform guard skips zero K-tiles ----
        float h[2][4][4];
        #pragma unroll
        for (int mt = 0; mt < 2; ++mt)
            #pragma unroll
            for (int nt = 0; nt < 4; ++nt)
                #pragma unroll
                for (int e = 0; e < 4; ++e) h[mt][nt][e] = 0.0f;

        {
            const uint4* XF  = (const uint4*)(sm + OFF_X);
            const uint4* WpF = (const uint4*)(sm + OFF_WP);
            #pragma unroll
            for (int kt = 0; kt < 16; ++kt) {
                if (2 * kt < fw) {       // uniform; skipped tiles are exact zeros
                    const uint4 a0 = XF[((warp * 2 + 0) * 16 + kt) * 32 + lane];
                    const uint4 a1 = XF[((warp * 2 + 1) * 16 + kt) * 32 + lane];
                    #pragma unroll
                    for (int np = 0; np < 2; ++np) {
                        const uint4 b = WpF[(kt * 2 + np) * 32 + lane];
                        mma8(h[0][np * 2],     a0, b.x, b.y);
                        mma8(h[1][np * 2],     a1, b.x, b.y);
                        mma8(h[0][np * 2 + 1], a0, b.z, b.w);
                        mma8(h[1][np * 2 + 1], a1, b.z, b.w);
                    }
                }
            }
        }

        // ---- repack H (+b_pre, tf32) into GEMM2 A-fragment layout (warp-private) ----
        #pragma unroll
        for (int e = 0; e < 4; ++e) {
            const int lane2 = (lane & 0x1C) | ((lane & 1) << 1) | (e & 1);
            const int reg2  = (((lane >> 1) & 1) << 1) | (e >> 1);
            const int col   = ((lane & 3) << 1) | (e & 1);
            #pragma unroll
            for (int mt = 0; mt < 2; ++mt)
                #pragma unroll
                for (int nt = 0; nt < 4; ++nt) {   // k-tiles of GEMM2 (D dense)
                    const int d = nt * 8 + col;
                    const float v = h[mt][nt][e] + bpre_sh[d];
                    sm[OFF_H + ((((warp * 2 + mt) * 4 + nt) * 32 + lane2) << 2) + reg2] = f2tf(v);
                }
        }
        __syncwarp();

        // ---- GEMM2: Y += H * Wpost; unrolled, uniform guard skips dead N-pairs ----
        {
            const uint4* HF  = (const uint4*)(sm + OFF_H);
            const uint4* WqF = (const uint4*)(sm + OFF_WQ);
            #pragma unroll
            for (int kt = 0; kt < 4; ++kt) {
                const uint4 a0 = HF[((warp * 2 + 0) * 4 + kt) * 32 + lane];
                const uint4 a1 = HF[((warp * 2 + 1) * 4 + kt) * 32 + lane];
                #pragma unroll
                for (int np = 0; np < 8; ++np) {
                    if (4 * np < fw) {   // uniform; outputs beyond fw never stored
                        const uint4 b = WqF[(kt * 8 + np) * 32 + lane];
                        mma8(yacc[0][np * 2],     a0, b.x, b.y);
                        mma8(yacc[1][np * 2],     a1, b.x, b.y);
                        mma8(yacc[0][np * 2 + 1], a0, b.z, b.w);
                        mma8(yacc[1][np * 2 + 1], a1, b.z, b.w);
                    }
                }
            }
        }
    }

    // ---- epilogue: stage Y in smem (reuse X/WP region), then coalesced scatter ----
    __syncthreads();
    float* Ybuf = (float*)sm;   // [m][c][w] : m stride 132, c stride 33 (16896 <= 28672)
    #pragma unroll
    for (int e = 0; e < 4; ++e) {
        const int r   = (lane >> 2) + ((e >> 1) << 3);
        const int col = ((lane & 3) << 1) | (e & 1);
        #pragma unroll
        for (int mt = 0; mt < 2; ++mt) {
            const int m = warp * 32 + mt * 16 + r;
            #pragma unroll
            for (int nt = 0; nt < 16; ++nt) {
                if (2 * nt < fw) {
                    const int o = nt * 8 + col;
                    Ybuf[m * 132 + (o & 3) * 33 + (o >> 2)] = yacc[mt][nt][e] + bpost_sh[o];
                }
            }
        }
    }
    __syncthreads();

    for (int task = warp; task < MT * Cc; task += 4) {
        const int m  = task >> 2;
        const int c  = task & 3;
        const int mg = tile0 + m;
        const int w  = lane;
        if (mg < Mrows && w < fw) {
            const int b = mg / Tt;
            const int t = mg - b * Tt;
            out[((size_t)(b * Cc + c) * Tt + t) * FQn + fs + w] = Ybuf[m * 132 + c * 33 + w];
        }
    }
}

extern "C" void kernel_launch(void* const* d_in, const int* in_sizes, int n_in,
                              void* d_out, int out_size)
{
    (void)in_sizes; (void)n_in; (void)out_size;
    const float* x      = (const float*)d_in[0];
    const float* w_pre  = (const float*)d_in[1];
    const float* b_pre  = (const float*)d_in[2];
    const float* w_post = (const float*)d_in[3];
    const float* b_post = (const float*)d_in[4];
    float* out = (float*)d_out;

    const size_t smem_bytes = (size_t)SMEM_U32 * sizeof(uint32_t);  // 112 KB
    cudaFuncSetAttribute(bandsplit_mma,
                         cudaFuncAttributeMaxDynamicSharedMemorySize,
                         (int)smem_bytes);

    dim3 grid((Mrows + MT - 1) / MT, KB);   // (63, 45)
    bandsplit_mma<<<grid, THREADS, smem_bytes>>>(x, w_pre, b_pre, w_post, b_post, out);
}

// round 10
// speedup vs baseline: 2.8879x; 2.3880x over previous
#include <cuda_runtime.h>
#include <cstdint>

#define THREADS 256

// ---- problem constants ----
#define Cc    4
#define Tt    1000
#define FQn   1025
#define Dd    384
#define INF   128      // W*C
#define Mrows 8000     // B*T
#define KB    45

// ---- tiling ----
#define MT    256      // rows per CTA (8 warps x 32 rows)
#define DC    32       // D chunk
#define NCH   (Dd / DC)   // 12

// ---- smem layout (uint32 units), MMA fragment order, weights double-buffered ----
#define OFF_X   0
#define SZ_X    (16*16*128)     // 32768
#define OFF_WP  (OFF_X + SZ_X)
#define SZ_WP1  (16*2*128)      // 4096 per buffer
#define OFF_WQ  (OFF_WP + 2*SZ_WP1)
#define SZ_WQ1  (4*8*128)       // 4096 per buffer
#define OFF_H   (OFF_WQ + 2*SZ_WQ1)
#define SZ_H    (16*4*128)      // 8192
#define SMEM_U32 (OFF_H + SZ_H)      // 57344 u32 = 224 KB

// Band tables (disjoint frequency groups)
__constant__ int c_start[KB] = {
    0,4,9,15,22,30,39,49,60,72,85,99,114,130,147,165,184,204,225,247,
    270,294,319,345,372,400,429,459,490,522,554,586,618,650,682,714,
    746,778,810,842,874,906,938,970,1002};
__constant__ int c_width[KB] = {
    4,5,6,7,8,9,10,11,12,13,14,15,16,17,18,19,20,21,22,23,
    24,25,26,27,28,29,30,31,32,32,32,32,32,32,32,32,
    32,32,32,32,32,32,32,32,23};

__device__ __forceinline__ uint32_t f2tf(float f) {
    uint32_t r;
    asm("cvt.rna.tf32.f32 %0, %1;" : "=r"(r) : "f"(f));
    return r;
}

__device__ __forceinline__ void mma8(float* c, const uint4 a, uint32_t b0, uint32_t b1) {
    asm volatile(
        "mma.sync.aligned.m16n8k8.row.col.f32.tf32.tf32.f32 "
        "{%0,%1,%2,%3},{%4,%5,%6,%7},{%8,%9},{%0,%1,%2,%3};"
        : "+f"(c[0]), "+f"(c[1]), "+f"(c[2]), "+f"(c[3])
        : "r"(a.x), "r"(a.y), "r"(a.z), "r"(a.w), "r"(b0), "r"(b1));
}

__global__ __launch_bounds__(THREADS, 1)
void bandsplit_mma(const float* __restrict__ x,
                   const float* __restrict__ w_pre,
                   const float* __restrict__ b_pre,
                   const float* __restrict__ w_post,
                   const float* __restrict__ b_post,
                   float* __restrict__ out)
{
    extern __shared__ uint32_t sm[];
    __shared__ float bpre_sh[2][DC];
    __shared__ float bpost_sh[INF];

    const int k     = blockIdx.y;
    const int tile0 = blockIdx.x * MT;
    const int tid   = threadIdx.x;
    const int warp  = tid >> 5;
    const int lane  = tid & 31;
    const int fs    = c_start[k];
    const int fw    = c_width[k];

    for (int i = tid; i < INF; i += THREADS) bpost_sh[i] = b_post[k * INF + i];

    // ---- gather X into A-fragment layout (tf32) ----
    for (int task = warp; task < MT * Cc; task += 8) {
        const int m  = task >> 2;
        const int c  = task & 3;
        const int mg = tile0 + m;
        const int w  = lane;
        float v = 0.0f;
        if (mg < Mrows && w < fw) {
            const int b = mg / Tt;
            const int t = mg - b * Tt;
            v = x[((size_t)(b * Cc + c) * Tt + t) * FQn + fs + w];
        }
        const int kt     = w >> 1;
        const int gm     = m >> 4;
        const int lane_s = ((m & 7) << 2) | c;
        const int reg    = ((w & 1) << 1) | ((m >> 3) & 1);
        sm[OFF_X + (((gm * 16 + kt) * 32 + lane_s) << 2) + reg] = f2tf(v);
    }

    // ---- register prefetch of weight chunks (16+16 floats per thread) ----
    float wp_r[16], wq_r[16], bp_r;

    auto ldg_chunk = [&](int ch) {
        const int dbase = ch * DC;
        #pragma unroll
        for (int j = 0; j < 16; ++j) {          // w_pre: 128 rows x 32 cols
            const int i  = j * THREADS + tid;   // coalesced 128B per warp
            const int kk = i >> 5;
            const int d  = i & 31;
            wp_r[j] = w_pre[((size_t)k * INF + kk) * Dd + dbase + d];
        }
        #pragma unroll
        for (int j = 0; j < 16; ++j) {          // w_post: 32 rows x 128 cols
            const int i = j * THREADS + tid;
            const int d = i >> 7;
            const int o = i & 127;
            wq_r[j] = w_post[((size_t)k * Dd + dbase + d) * INF + o];
        }
        bp_r = (tid < DC) ? b_pre[k * Dd + dbase + tid] : 0.0f;
    };

    auto sts_chunk = [&](int bsel) {
        uint32_t* WP = sm + OFF_WP + bsel * SZ_WP1;
        uint32_t* WQ = sm + OFF_WQ + bsel * SZ_WQ1;
        #pragma unroll
        for (int j = 0; j < 16; ++j) {
            const int i  = j * THREADS + tid;
            const int kk = i >> 5;
            const int d  = i & 31;
            const int kt = kk >> 3, kr = kk & 7, nt = d >> 3, nc = d & 7;
            const int np = nt >> 1, p = nt & 1;
            const int lane_s = (nc << 2) | (kr & 3);
            const int reg    = (p << 1) | (kr >> 2);
            WP[(((kt * 2 + np) * 32 + lane_s) << 2) + reg] = f2tf(wp_r[j]);
        }
        #pragma unroll
        for (int j = 0; j < 16; ++j) {
            const int i = j * THREADS + tid;
            const int d = i >> 7;
            const int o = i & 127;
            const int kt = d >> 3, kr = d & 7, nt = o >> 3, nc = o & 7;
            const int np = nt >> 1, p = nt & 1;
            const int lane_s = (nc << 2) | (kr & 3);
            const int reg    = (p << 1) | (kr >> 2);
            WQ[(((kt * 8 + np) * 32 + lane_s) << 2) + reg] = f2tf(wq_r[j]);
        }
        if (tid < DC) bpre_sh[bsel][tid] = bp_r;
    };

    // GEMM2 accumulators: 2 m-tiles x 16 n-tiles x 4 regs
    float yacc[2][16][4];
    #pragma unroll
    for (int mt = 0; mt < 2; ++mt)
        #pragma unroll
        for (int nt = 0; nt < 16; ++nt)
            #pragma unroll
            for (int e = 0; e < 4; ++e) yacc[mt][nt][e] = 0.0f;

    // prologue: stage chunk 0; barrier also covers X gather
    ldg_chunk(0);
    sts_chunk(0);
    __syncthreads();

    int buf = 0;
    for (int ch = 0; ch < NCH; ++ch) {
        // issue next chunk's LDGs now; first use (STS) is after GEMM2
        if (ch + 1 < NCH) ldg_chunk(ch + 1);

        const uint32_t* WP = sm + OFF_WP + buf * SZ_WP1;
        const uint32_t* WQ = sm + OFF_WQ + buf * SZ_WQ1;

        // ---- GEMM1: H[32 x DC] per warp, K = 128 ----
        float h[2][4][4];
        #pragma unroll
        for (int mt = 0; mt < 2; ++mt)
            #pragma unroll
            for (int nt = 0; nt < 4; ++nt)
                #pragma unroll
                for (int e = 0; e < 4; ++e) h[mt][nt][e] = 0.0f;

        {
            const uint4* XF  = (const uint4*)(sm + OFF_X);
            const uint4* WpF = (const uint4*)WP;
            #pragma unroll
            for (int kt = 0; kt < 16; ++kt) {
                const uint4 a0 = XF[((warp * 2 + 0) * 16 + kt) * 32 + lane];
                const uint4 a1 = XF[((warp * 2 + 1) * 16 + kt) * 32 + lane];
                #pragma unroll
                for (int np = 0; np < 2; ++np) {
                    const uint4 b = WpF[(kt * 2 + np) * 32 + lane];
                    mma8(h[0][np * 2],     a0, b.x, b.y);
                    mma8(h[1][np * 2],     a1, b.x, b.y);
                    mma8(h[0][np * 2 + 1], a0, b.z, b.w);
                    mma8(h[1][np * 2 + 1], a1, b.z, b.w);
                }
            }
        }

        // ---- repack H (+b_pre, tf32) into GEMM2 A-fragment layout (warp-private) ----
        #pragma unroll
        for (int e = 0; e < 4; ++e) {
            const int lane2 = (lane & 0x1C) | ((lane & 1) << 1) | (e & 1);
            const int reg2  = (((lane >> 1) & 1) << 1) | (e >> 1);
            const int col   = ((lane & 3) << 1) | (e & 1);
            #pragma unroll
            for (int mt = 0; mt < 2; ++mt)
                #pragma unroll
                for (int nt = 0; nt < 4; ++nt) {
                    const int d = nt * 8 + col;
                    const float v = h[mt][nt][e] + bpre_sh[buf][d];
                    sm[OFF_H + ((((warp * 2 + mt) * 4 + nt) * 32 + lane2) << 2) + reg2] = f2tf(v);
                }
        }
        __syncwarp();

        // ---- GEMM2: Y[32 x 128] += H[32 x DC] * Wpost[DC x 128] ----
        {
            const uint4* HF  = (const uint4*)(sm + OFF_H);
            const uint4* WqF = (const uint4*)WQ;
            #pragma unroll
            for (int kt = 0; kt < 4; ++kt) {
                const uint4 a0 = HF[((warp * 2 + 0) * 4 + kt) * 32 + lane];
                const uint4 a1 = HF[((warp * 2 + 1) * 4 + kt) * 32 + lane];
                #pragma unroll
                for (int np = 0; np < 8; ++np) {
                    const uint4 b = WqF[(kt * 8 + np) * 32 + lane];
                    mma8(yacc[0][np * 2],     a0, b.x, b.y);
                    mma8(yacc[1][np * 2],     a1, b.x, b.y);
                    mma8(yacc[0][np * 2 + 1], a0, b.z, b.w);
                    mma8(yacc[1][np * 2 + 1], a1, b.z, b.w);
                }
            }
        }

        // store prefetched chunk into the other buffer, then ONE barrier
        if (ch + 1 < NCH) sts_chunk(buf ^ 1);
        __syncthreads();
        buf ^= 1;
    }

    // ---- epilogue: stage Y in smem (reuse X/WP region), then coalesced scatter ----
    float* Ybuf = (float*)sm;   // [m][c][w] : m stride 132, c stride 33 (33792 <= 57344)
    #pragma unroll
    for (int e = 0; e < 4; ++e) {
        const int r   = (lane >> 2) + ((e >> 1) << 3);
        const int col = ((lane & 3) << 1) | (e & 1);
        #pragma unroll
        for (int mt = 0; mt < 2; ++mt) {
            const int m = warp * 32 + mt * 16 + r;
            #pragma unroll
            for (int nt = 0; nt < 16; ++nt) {
                const int o = nt * 8 + col;
                Ybuf[m * 132 + (o & 3) * 33 + (o >> 2)] = yacc[mt][nt][e] + bpost_sh[o];
            }
        }
    }
    __syncthreads();

    for (int task = warp; task < MT * Cc; task += 8) {
        const int m  = task >> 2;
        const int c  = task & 3;
        const int mg = tile0 + m;
        const int w  = lane;
        if (mg < Mrows && w < fw) {
            const int b = mg / Tt;
            const int t = mg - b * Tt;
            out[((size_t)(b * Cc + c) * Tt + t) * FQn + fs + w] = Ybuf[m * 132 + c * 33 + w];
        }
    }
}

extern "C" void kernel_launch(void* const* d_in, const int* in_sizes, int n_in,
                              void* d_out, int out_size)
{
    (void)in_sizes; (void)n_in; (void)out_size;
    const float* x      = (const float*)d_in[0];
    const float* w_pre  = (const float*)d_in[1];
    const float* b_pre  = (const float*)d_in[2];
    const float* w_post = (const float*)d_in[3];
    const float* b_post = (const float*)d_in[4];
    float* out = (float*)d_out;

    const size_t smem_bytes = (size_t)SMEM_U32 * sizeof(uint32_t);  // 224 KB
    cudaFuncSetAttribute(bandsplit_mma,
                         cudaFuncAttributeMaxDynamicSharedMemorySize,
                         (int)smem_bytes);

    dim3 grid((Mrows + MT - 1) / MT, KB);   // (32, 45)
    bandsplit_mma<<<grid, THREADS, smem_bytes>>>(x, w_pre, b_pre, w_post, b_post, out);
}